// round 4
// baseline (speedup 1.0000x reference)
#include <cuda_runtime.h>
#include <cuda_fp16.h>
#include <cstdint>

// out[bn] = A @ x[bn]^T @ B, fused, legacy mma.sync (fp16 in / f32 acc).
// G1: T[a=64, p=208pad] = sum_c A[a,c] x[p,c]   (K=768, 24 chunks of 32)
// G2: out[a,h] = sum_p T[a,p] B[p,h]            (K=208, pad zero)
#define P_DIM 196
#define C_DIM 768
#define KC 32
#define NCH (C_DIM / KC)          // 24
#define PP 208                    // padded p
#define XPITCH 40                 // halves per row (80 B, 16B-aligned rows)
#define TPITCH 216                // halves per row (432 B)

#define ABUF_BYTES (64 * XPITCH * 2)    // 5120
#define XBUF_BYTES (PP * XPITCH * 2)    // 16640
#define OFF_AS 0
#define OFF_XS (2 * ABUF_BYTES)                  // 10240
#define OFF_TS (OFF_XS + 2 * XBUF_BYTES)         // 43520
#define OFF_BS (OFF_TS + 64 * TPITCH * 2)        // 71168
#define SMEM_BYTES (OFF_BS + 64 * TPITCH * 2)    // 98816

#define DEVINL __device__ __forceinline__

DEVINL uint32_t smem_u32(const void* p) {
    uint32_t a;
    asm("{ .reg .u64 t; cvta.to.shared.u64 t, %1; cvt.u32.u64 %0, t; }" : "=r"(a) : "l"(p));
    return a;
}

DEVINL uint32_t f2h2(float lo, float hi) {
    __half2 h = __floats2half2_rn(lo, hi);
    return *reinterpret_cast<uint32_t*>(&h);
}

DEVINL void ldsm4(uint32_t* r, uint32_t addr) {
    asm volatile("ldmatrix.sync.aligned.m8n8.x4.shared.b16 {%0,%1,%2,%3}, [%4];"
                 : "=r"(r[0]), "=r"(r[1]), "=r"(r[2]), "=r"(r[3]) : "r"(addr));
}
DEVINL void ldsm2(uint32_t* r, uint32_t addr) {
    asm volatile("ldmatrix.sync.aligned.m8n8.x2.shared.b16 {%0,%1}, [%2];"
                 : "=r"(r[0]), "=r"(r[1]) : "r"(addr));
}
DEVINL void mma16816(float* d, const uint32_t* a, const uint32_t* b) {
    asm volatile("mma.sync.aligned.m16n8k16.row.col.f32.f16.f16.f32 "
                 "{%0,%1,%2,%3}, {%4,%5,%6,%7}, {%8,%9}, {%0,%1,%2,%3};"
                 : "+f"(d[0]), "+f"(d[1]), "+f"(d[2]), "+f"(d[3])
                 : "r"(a[0]), "r"(a[1]), "r"(a[2]), "r"(a[3]), "r"(b[0]), "r"(b[1]));
}

__global__ void __launch_bounds__(256, 1) sepnet_fused_kernel(
    const float* __restrict__ x, const float* __restrict__ Amat,
    const float* __restrict__ Bmat, float* __restrict__ out)
{
    extern __shared__ char smem[];
    const uint32_t sb = smem_u32(smem);
    const int tid = threadIdx.x;
    const int wid = tid >> 5;
    const int lane = tid & 31;
    const int bn = blockIdx.x;
    const float* xb = x + (size_t)bn * (P_DIM * C_DIM);

    // ---- one-time setup: Bs[h][p] (f16, transposed, pad p>=196 zero) ----
    for (int idx = tid; idx < 64 * PP; idx += 256) {
        int p = idx >> 6, h = idx & 63;
        float v = (p < P_DIM) ? Bmat[p * 64 + h] : 0.0f;
        *reinterpret_cast<__half*>(smem + OFF_BS + (h * TPITCH + p) * 2) = __float2half_rn(v);
    }
    // zero Xs pad rows (196..207) in both buffers: 2 * 12 rows * 80 B = 1920 B
    for (int idx = tid; idx < 480; idx += 256) {
        int buf = idx / 240, o = idx % 240;
        *reinterpret_cast<uint32_t*>(smem + OFF_XS + buf * XBUF_BYTES + P_DIM * 80 + o * 4) = 0u;
    }

    // ---- G1 accumulators: warp (wid>>1) owns a-rows, (wid&1) owns p-half ----
    float acc[13][4];
#pragma unroll
    for (int i = 0; i < 13; i++) {
        acc[i][0] = acc[i][1] = acc[i][2] = acc[i][3] = 0.0f;
    }

    const int arow = (wid >> 1) * 16 + (lane & 15);     // A-frag row
    const int acolofs = (lane & 16) ? 8 : 0;            // A-frag col offset
    const int phalf = (wid & 1) * 104;                  // p-half base
    const int browofs = (lane & 7) + ((lane & 16) >> 1);// B-frag row offset (x4)
    const int bcolofs = ((lane >> 3) & 1) * 8;          // B-frag col offset (x4)

    float4 xr[7], ar[2];

    // prologue loads (chunk 0)
#pragma unroll
    for (int i = 0; i < 6; i++) {
        int idx = i * 256 + tid, row = idx >> 3, c4 = idx & 7;
        xr[i] = *reinterpret_cast<const float4*>(xb + row * C_DIM + c4 * 4);
    }
    if (tid < 32) {
        int idx = 1536 + tid, row = idx >> 3, c4 = idx & 7;
        xr[6] = *reinterpret_cast<const float4*>(xb + row * C_DIM + c4 * 4);
    }
#pragma unroll
    for (int i = 0; i < 2; i++) {
        int idx = i * 256 + tid, row = idx >> 3, c4 = idx & 7;
        ar[i] = *reinterpret_cast<const float4*>(Amat + row * C_DIM + c4 * 4);
    }

    for (int ch = 0; ch < NCH; ch++) {
        const int buf = ch & 1;
        // ---- cvt + STS staged regs into buf (4 halves = 8 bytes per float4) ----
        {
            char* xsb = smem + OFF_XS + buf * XBUF_BYTES;
#pragma unroll
            for (int i = 0; i < 6; i++) {
                int idx = i * 256 + tid, row = idx >> 3, c4 = idx & 7;
                uint32_t* d = reinterpret_cast<uint32_t*>(xsb + row * 80 + c4 * 8);
                d[0] = f2h2(xr[i].x, xr[i].y);
                d[1] = f2h2(xr[i].z, xr[i].w);
            }
            if (tid < 32) {
                int idx = 1536 + tid, row = idx >> 3, c4 = idx & 7;
                uint32_t* d = reinterpret_cast<uint32_t*>(xsb + row * 80 + c4 * 8);
                d[0] = f2h2(xr[6].x, xr[6].y);
                d[1] = f2h2(xr[6].z, xr[6].w);
            }
            char* asb = smem + OFF_AS + buf * ABUF_BYTES;
#pragma unroll
            for (int i = 0; i < 2; i++) {
                int idx = i * 256 + tid, row = idx >> 3, c4 = idx & 7;
                uint32_t* d = reinterpret_cast<uint32_t*>(asb + row * 80 + c4 * 8);
                d[0] = f2h2(ar[i].x, ar[i].y);
                d[1] = f2h2(ar[i].z, ar[i].w);
            }
        }
        __syncthreads();

        // ---- issue next chunk's LDGs (latency hides under mma below) ----
        if (ch + 1 < NCH) {
            const float* xc = xb + (ch + 1) * KC;
            const float* ac = Amat + (ch + 1) * KC;
#pragma unroll
            for (int i = 0; i < 6; i++) {
                int idx = i * 256 + tid, row = idx >> 3, c4 = idx & 7;
                xr[i] = *reinterpret_cast<const float4*>(xc + row * C_DIM + c4 * 4);
            }
            if (tid < 32) {
                int idx = 1536 + tid, row = idx >> 3, c4 = idx & 7;
                xr[6] = *reinterpret_cast<const float4*>(xc + row * C_DIM + c4 * 4);
            }
#pragma unroll
            for (int i = 0; i < 2; i++) {
                int idx = i * 256 + tid, row = idx >> 3, c4 = idx & 7;
                ar[i] = *reinterpret_cast<const float4*>(ac + row * C_DIM + c4 * 4);
            }
        }

        // ---- mma over buf ----
        {
            const uint32_t asb = sb + OFF_AS + buf * ABUF_BYTES;
            const uint32_t xsb = sb + OFF_XS + buf * XBUF_BYTES;
#pragma unroll
            for (int ks = 0; ks < 2; ks++) {
                const int k0 = ks * 16;
                uint32_t a[4];
                ldsm4(a, asb + (arow * XPITCH + k0 + acolofs) * 2);
#pragma unroll
                for (int g = 0; g < 6; g++) {
                    uint32_t b[4];
                    ldsm4(b, xsb + ((phalf + g * 16 + browofs) * XPITCH + k0 + bcolofs) * 2);
                    mma16816(acc[2 * g], a, &b[0]);
                    mma16816(acc[2 * g + 1], a, &b[2]);
                }
                uint32_t b2[2];
                ldsm2(b2, xsb + ((phalf + 96 + (lane & 7)) * XPITCH + k0 + ((lane & 8) ? 8 : 0)) * 2);
                mma16816(acc[12], a, b2);
            }
        }
        __syncthreads();
    }

    // ---- store T (f16) to SMEM [a][p] ----
    {
        char* ts = smem + OFF_TS;
        const int r0 = (wid >> 1) * 16 + lane / 4;
        const int cb = phalf + (lane & 3) * 2;
#pragma unroll
        for (int nt = 0; nt < 13; nt++) {
            int c = cb + nt * 8;
            *reinterpret_cast<uint32_t*>(ts + (r0 * TPITCH + c) * 2) = f2h2(acc[nt][0], acc[nt][1]);
            *reinterpret_cast<uint32_t*>(ts + ((r0 + 8) * TPITCH + c) * 2) = f2h2(acc[nt][2], acc[nt][3]);
        }
    }
    __syncthreads();

    // ---- G2: out[a,h] = sum_p T[a,p] B[p,h], K = 208 ----
    float o[4][4];
#pragma unroll
    for (int i = 0; i < 4; i++) {
        o[i][0] = o[i][1] = o[i][2] = o[i][3] = 0.0f;
    }
    const uint32_t tsb = sb + OFF_TS;
    const uint32_t bsb = sb + OFF_BS;
    const int a2row = (wid >> 1) * 16 + (lane & 15);
    const int a2co = (lane & 16) ? 8 : 0;
    const int hhalf = (wid & 1) * 32;
#pragma unroll
    for (int ks = 0; ks < 13; ks++) {
        const int k0 = ks * 16;
        uint32_t a[4];
        ldsm4(a, tsb + (a2row * TPITCH + k0 + a2co) * 2);
#pragma unroll
        for (int g = 0; g < 2; g++) {
            uint32_t b[4];
            ldsm4(b, bsb + ((hhalf + g * 16 + browofs) * TPITCH + k0 + bcolofs) * 2);
            mma16816(o[2 * g], a, &b[0]);
            mma16816(o[2 * g + 1], a, &b[2]);
        }
    }

    // ---- epilogue ----
    {
        float* ob = out + (size_t)bn * 4096;
        const int r0 = (wid >> 1) * 16 + lane / 4;
        const int cb = hhalf + (lane & 3) * 2;
#pragma unroll
        for (int nt = 0; nt < 4; nt++) {
            int c = cb + nt * 8;
            *reinterpret_cast<float2*>(ob + r0 * 64 + c) = make_float2(o[nt][0], o[nt][1]);
            *reinterpret_cast<float2*>(ob + (r0 + 8) * 64 + c) = make_float2(o[nt][2], o[nt][3]);
        }
    }
}

extern "C" void kernel_launch(void* const* d_in, const int* in_sizes, int n_in,
                              void* d_out, int out_size) {
    int ix = 0, ia = 1, ib = 2;
    for (int i = 0; i < n_in; i++) {
        if (in_sizes[i] == 237244416) ix = i;
        else if (in_sizes[i] == 49152) ia = i;
        else if (in_sizes[i] == 12544) ib = i;
    }
    const float* x = (const float*)d_in[ix];
    const float* A = (const float*)d_in[ia];
    const float* B = (const float*)d_in[ib];
    float* out = (float*)d_out;

    cudaFuncSetAttribute(sepnet_fused_kernel,
                         cudaFuncAttributeMaxDynamicSharedMemorySize, SMEM_BYTES);
    sepnet_fused_kernel<<<1576, 256, SMEM_BYTES>>>(x, A, B, out);
}